// round 15
// baseline (speedup 1.0000x reference)
#include <cuda_runtime.h>
#include <math.h>

#define BB 16
#define SS 8
#define CC 3
#define KK 6
#define HW 16384
#define CHUNK 256
#define NCHUNK (HW/CHUNK)     // 64
#define NTHREADS 288          // 9 warps
#define EPSF 1.1920928955078125e-07f

// slot layout (per chunk):
//   F/XX: s*108 + k*18 + j   (j<12: F[a][b], 12..17: XX sym3)  [0,864)
//   Sec:  864 + k*11 + j     (j<10: sym4 Sec, j=10: gp sum)    [864,930)
// Each slot stores 2 sub-partials (4-level warp reduction) as one float2.
#define NSLOT 930

__device__ float2 g_part2[(size_t)BB*NCHUNK*NSLOT];  // [u][chunk][slot] float2
__device__ float  g_ops[BB*SS*KK*12];
__device__ float  g_siginv[BB*SS*KK*8];      // [s00,s01,s02,s11,s12,s22,0,0]
__device__ float  g_ldsum[BB*KK];

// ---------------- packed f32x2 helpers ----------------
typedef unsigned long long u64;
__device__ __forceinline__ u64 pk2(float lo, float hi) {
    u64 r; asm("mov.b64 %0,{%1,%2};" : "=l"(r) : "f"(lo), "f"(hi)); return r;
}
__device__ __forceinline__ u64 bc2(float v) { return pk2(v, v); }
__device__ __forceinline__ void up2(float& lo, float& hi, u64 v) {
    asm("mov.b64 {%0,%1},%2;" : "=f"(lo), "=f"(hi) : "l"(v));
}
__device__ __forceinline__ u64 fma2(u64 a, u64 b, u64 c) {
    u64 d; asm("fma.rn.f32x2 %0,%1,%2,%3;" : "=l"(d) : "l"(a), "l"(b), "l"(c)); return d;
}
__device__ __forceinline__ u64 mul2(u64 a, u64 b) {
    u64 d; asm("mul.rn.f32x2 %0,%1,%2;" : "=l"(d) : "l"(a), "l"(b)); return d;
}
__device__ __forceinline__ u64 add2(u64 a, u64 b) {
    u64 d; asm("add.rn.f32x2 %0,%1,%2;" : "=l"(d) : "l"(a), "l"(b)); return d;
}
__device__ __forceinline__ u64 neg2(u64 a) { return a ^ 0x8000000080000000ULL; }

// 4-level partial warp reduction: lanes 0-1 end with sums of even/odd lane groups
__device__ __forceinline__ u64 red4lvl(u64 v) {
    v = add2(v, __shfl_down_sync(0xffffffffu, v, 16));
    v = add2(v, __shfl_down_sync(0xffffffffu, v, 8));
    v = add2(v, __shfl_down_sync(0xffffffffu, v, 4));
    v = add2(v, __shfl_down_sync(0xffffffffu, v, 2));
    return v;
}

// MODE 0: softmax(pred) -> gp, accumulate moments
// MODE 1: quad -> gen -> softmax(pred+gen) -> gp, accumulate moments
// MODE 2: quad -> gen -> write output
template<int MODE>
__global__ __launch_bounds__(NTHREADS, 2)
void accum_kernel(const float* __restrict__ img, const float* __restrict__ shifted,
                  const float* __restrict__ pred, float* __restrict__ out)
{
    __shared__ float4 s_sh[SS][CHUNK];     // 32 KB
    __shared__ float4 s_img[CHUNK];        // 4 KB
    __shared__ u64   s_gp2[3][CHUNK];      // 6 KB  (k-pairs packed)
    __shared__ u64   s_ops2[SS*3*12];      // 2.25 KB
    __shared__ u64   s_sinv2[SS*3*6];      // 1.125 KB
    __shared__ float s_ld[KK];

    const int u    = blockIdx.y;
    const int base = blockIdx.x * CHUNK;
    const int tid  = threadIdx.x;

    if (MODE >= 1) {
        const float* go = g_ops + u*SS*KK*12;
        for (int i = tid; i < SS*3*12; i += NTHREADS) {
            const int m = i/12, j = i%12;
            const int s = m/3, kk = m%3;
            s_ops2[i] = pk2(go[(s*KK + 2*kk)*12 + j], go[(s*KK + 2*kk + 1)*12 + j]);
        }
        const float* gs = g_siginv + u*SS*KK*8;
        for (int i = tid; i < SS*3*6; i += NTHREADS) {
            const int m = i/6, j = i%6;
            const int s = m/3, kk = m%3;
            const float sc = (j==1 || j==2 || j==4) ? 2.f : 1.f;
            s_sinv2[i] = pk2(sc*gs[(s*KK + 2*kk)*8 + j], sc*gs[(s*KK + 2*kk + 1)*8 + j]);
        }
        if (tid < KK) s_ld[tid] = g_ldsum[u*KK + tid];
        __syncthreads();
    }

    const float* imgU  = img + (size_t)u*CC*HW;
    const float* shU   = shifted + (size_t)u*SS*CC*HW;
    const float* predU = pred + (size_t)u*KK*HW;

    // ---- phase 1: per-pixel quad / softmax / SMEM staging ----
    if (tid < CHUNK) {
        const int pix = base + tid;
        const float pb0 = imgU[pix];
        const float pb1 = imgU[HW + pix];
        const float pb2 = imgU[2*HW + pix];
        if (MODE < 2) s_img[tid] = make_float4(pb0, pb1, pb2, 1.f);

        const u64 pbb0 = bc2(pb0), pbb1 = bc2(pb1), pbb2 = bc2(pb2);
        u64 q2[3] = {0ULL, 0ULL, 0ULL};

        #pragma unroll
        for (int s = 0; s < SS; s++) {
            const float x0 = shU[(s*CC+0)*HW + pix];
            const float x1 = shU[(s*CC+1)*HW + pix];
            const float x2 = shU[(s*CC+2)*HW + pix];
            if (MODE < 2) s_sh[s][tid] = make_float4(x0, x1, x2, 0.f);
            if (MODE >= 1) {
                const u64 xb0 = bc2(x0), xb1 = bc2(x1), xb2 = bc2(x2);
                #pragma unroll
                for (int kk = 0; kk < 3; kk++) {
                    const u64* O = s_ops2 + (s*3 + kk)*12;
                    const u64 d0 = add2(xb0, neg2(fma2(O[0], pbb0, fma2(O[1], pbb1, fma2(O[2],  pbb2, O[3])))));
                    const u64 d1 = add2(xb1, neg2(fma2(O[4], pbb0, fma2(O[5], pbb1, fma2(O[6],  pbb2, O[7])))));
                    const u64 d2 = add2(xb2, neg2(fma2(O[8], pbb0, fma2(O[9], pbb1, fma2(O[10], pbb2, O[11])))));
                    const u64* Si = s_sinv2 + (s*3 + kk)*6;
                    u64 acc = q2[kk];
                    acc = fma2(Si[0], mul2(d0, d0), acc);
                    acc = fma2(Si[1], mul2(d0, d1), acc);
                    acc = fma2(Si[2], mul2(d0, d2), acc);
                    acc = fma2(Si[3], mul2(d1, d1), acc);
                    acc = fma2(Si[4], mul2(d1, d2), acc);
                    acc = fma2(Si[5], mul2(d2, d2), acc);
                    q2[kk] = acc;
                }
            }
        }

        float q[KK];
        #pragma unroll
        for (int kk = 0; kk < 3; kk++) up2(q[2*kk], q[2*kk+1], q2[kk]);

        if (MODE == 2) {
            #pragma unroll
            for (int k = 0; k < KK; k++)
                out[((size_t)u*KK + k)*HW + pix] = -0.5f*q[k] - 0.5f*s_ld[k];
        } else {
            float lg[KK];
            float mx = -1e30f;
            #pragma unroll
            for (int k = 0; k < KK; k++) {
                const float gen = (MODE >= 1) ? (-0.5f*q[k] - 0.5f*s_ld[k]) : 0.f;
                lg[k] = predU[k*HW + pix] + gen;
                mx = fmaxf(mx, lg[k]);
            }
            float sum = 0.f;
            #pragma unroll
            for (int k = 0; k < KK; k++) { lg[k] = __expf(lg[k] - mx); sum += lg[k]; }
            const float inv = 1.f / sum;
            #pragma unroll
            for (int kk = 0; kk < 3; kk++)
                s_gp2[kk][tid] = pk2(lg[2*kk]*inv + EPSF, lg[2*kk+1]*inv + EPSF);
        }
    }
    if (MODE == 2) return;
    __syncthreads();

    // ---- phase 2: packed moment accumulation ----
    const int warp = tid >> 5, lane = tid & 31;
    float* part = (float*)g_part2 + (size_t)(u*NCHUNK + blockIdx.x)*NSLOT*2;

    if (warp < SS) {
        const int s = warp;
        #pragma unroll 1
        for (int kk = 0; kk < 3; kk++) {
            u64 a[18];
            #pragma unroll
            for (int j = 0; j < 18; j++) a[j] = 0ULL;
            #pragma unroll
            for (int i = 0; i < CHUNK/32; i++) {
                const int p = lane + 32*i;
                const float4 x  = s_sh[s][p];
                const float4 pb = s_img[p];
                const u64 w2 = s_gp2[kk][p];
                const u64 xb0 = bc2(x.x),  xb1 = bc2(x.y),  xb2 = bc2(x.z);
                const u64 pbb0 = bc2(pb.x), pbb1 = bc2(pb.y), pbb2 = bc2(pb.z);
                const u64 t0 = mul2(xb0, w2), t1 = mul2(xb1, w2), t2 = mul2(xb2, w2);
                a[0]  = fma2(t0, pbb0, a[0]);  a[1]  = fma2(t0, pbb1, a[1]);
                a[2]  = fma2(t0, pbb2, a[2]);  a[3]  = add2(a[3], t0);
                a[4]  = fma2(t1, pbb0, a[4]);  a[5]  = fma2(t1, pbb1, a[5]);
                a[6]  = fma2(t1, pbb2, a[6]);  a[7]  = add2(a[7], t1);
                a[8]  = fma2(t2, pbb0, a[8]);  a[9]  = fma2(t2, pbb1, a[9]);
                a[10] = fma2(t2, pbb2, a[10]); a[11] = add2(a[11], t2);
                a[12] = fma2(t0, xb0, a[12]);  a[13] = fma2(t0, xb1, a[13]);
                a[14] = fma2(t0, xb2, a[14]);  a[15] = fma2(t1, xb1, a[15]);
                a[16] = fma2(t1, xb2, a[16]);  a[17] = fma2(t2, xb2, a[17]);
            }
            #pragma unroll
            for (int j = 0; j < 18; j++) {
                const u64 v = red4lvl(a[j]);
                if (lane < 2) {
                    float lo, hi; up2(lo, hi, v);
                    part[(size_t)(s*108 + (2*kk)*18 + j)*2 + lane]   = lo;
                    part[(size_t)(s*108 + (2*kk+1)*18 + j)*2 + lane] = hi;
                }
            }
        }
    } else {
        // warp 8: sym4 Sec moments + gp sums (packed k-pairs)
        #pragma unroll 1
        for (int kk = 0; kk < 3; kk++) {
            u64 a[10];
            #pragma unroll
            for (int j = 0; j < 10; j++) a[j] = 0ULL;
            #pragma unroll
            for (int i = 0; i < CHUNK/32; i++) {
                const int p = lane + 32*i;
                const float4 pb = s_img[p];
                const u64 w2 = s_gp2[kk][p];
                const u64 pbb0 = bc2(pb.x), pbb1 = bc2(pb.y), pbb2 = bc2(pb.z);
                const u64 ww0 = mul2(w2, pbb0), ww1 = mul2(w2, pbb1), ww2 = mul2(w2, pbb2);
                a[0] = fma2(ww0, pbb0, a[0]); a[1] = fma2(ww0, pbb1, a[1]);
                a[2] = fma2(ww0, pbb2, a[2]); a[3] = add2(a[3], ww0);
                a[4] = fma2(ww1, pbb1, a[4]); a[5] = fma2(ww1, pbb2, a[5]);
                a[6] = add2(a[6], ww1);
                a[7] = fma2(ww2, pbb2, a[7]); a[8] = add2(a[8], ww2);
                a[9] = add2(a[9], w2);
            }
            #pragma unroll
            for (int j = 0; j < 10; j++) {
                const u64 v = red4lvl(a[j]);
                if (lane < 2) {
                    float lo, hi; up2(lo, hi, v);
                    part[(size_t)(864 + (2*kk)*11 + j)*2 + lane]   = lo;
                    part[(size_t)(864 + (2*kk+1)*11 + j)*2 + lane] = hi;
                    if (j == 9) {  // gp sum duplicates Sec[3][3]
                        part[(size_t)(864 + (2*kk)*11 + 10)*2 + lane]   = lo;
                        part[(size_t)(864 + (2*kk+1)*11 + 10)*2 + lane] = hi;
                    }
                }
            }
        }
    }
}

// ---------------- fused reduce + per-u solve ----------------
// 4-way split serial reduce over chunks; each slot sums a float2/chunk.
__global__ __launch_bounds__(960)
void solve_kernel()
{
    __shared__ float s_q[4][NSLOT];
    __shared__ float m[NSLOT];
    __shared__ float s_Inv[KK][16];
    __shared__ float s_norm[KK];
    __shared__ float s_pn[KK];
    __shared__ float s_ld48[SS*KK];

    const int u = blockIdx.x;
    const int t = threadIdx.x;

    for (int idx = t; idx < 4*NSLOT; idx += 960) {
        const int qq = idx / NSLOT;
        const int slot = idx - qq*NSLOT;
        const float2* p = g_part2 + (size_t)(u*NCHUNK + qq*16)*NSLOT + slot;
        float v = 0.f;
        #pragma unroll
        for (int c = 0; c < 16; c++) {
            const float2 a = p[(size_t)c*NSLOT];
            v += (a.x + a.y);
        }
        s_q[qq][slot] = v;
    }
    __syncthreads();
    if (t < NSLOT) m[t] = ((s_q[0][t] + s_q[1][t]) + (s_q[2][t] + s_q[3][t]));
    __syncthreads();

    if (t < KK) {
        const int k = t;
        const float* sec = m + 864 + k*11;
        const float trace = sec[0] + sec[4] + sec[7] + sec[9];
        const float norm = 1.f / trace;
        s_norm[k] = norm;
        s_pn[k] = 1.f / sec[10];

        float M[4][4], Inv[4][4];
        M[0][0]=sec[0]; M[0][1]=sec[1]; M[0][2]=sec[2]; M[0][3]=sec[3];
        M[1][0]=sec[1]; M[1][1]=sec[4]; M[1][2]=sec[5]; M[1][3]=sec[6];
        M[2][0]=sec[2]; M[2][1]=sec[5]; M[2][2]=sec[7]; M[2][3]=sec[8];
        M[3][0]=sec[3]; M[3][1]=sec[6]; M[3][2]=sec[8]; M[3][3]=sec[9];
        for (int i = 0; i < 4; i++) {
            for (int j = 0; j < 4; j++) { M[i][j] *= norm; Inv[i][j] = (i==j)?1.f:0.f; }
            M[i][i] += EPSF;
        }
        for (int col = 0; col < 4; col++) {
            int piv = col; float best = fabsf(M[col][col]);
            for (int r = col+1; r < 4; r++) {
                const float v = fabsf(M[r][col]);
                if (v > best) { best = v; piv = r; }
            }
            if (piv != col) {
                for (int j = 0; j < 4; j++) {
                    float tmp=M[col][j]; M[col][j]=M[piv][j]; M[piv][j]=tmp;
                    tmp=Inv[col][j]; Inv[col][j]=Inv[piv][j]; Inv[piv][j]=tmp;
                }
            }
            const float d = 1.f / M[col][col];
            for (int j = 0; j < 4; j++) { M[col][j] *= d; Inv[col][j] *= d; }
            for (int r = 0; r < 4; r++) {
                if (r == col) continue;
                const float f = M[r][col];
                for (int j = 0; j < 4; j++) { M[r][j] -= f*M[col][j]; Inv[r][j] -= f*Inv[col][j]; }
            }
        }
        for (int i = 0; i < 16; i++) s_Inv[k][i] = Inv[i/4][i%4];
    }
    __syncthreads();

    if (t < SS*KK) {
        const int s = t / KK, k = t % KK;
        const float norm = s_norm[k];
        const float pn   = s_pn[k];
        const float* F  = m + s*108 + k*18;   // [3][4]
        const float* XX = F + 12;             // sym3
        const float* Sec10 = m + 864 + k*11;

        float Sec[4][4];
        Sec[0][0]=Sec10[0]; Sec[0][1]=Sec10[1]; Sec[0][2]=Sec10[2]; Sec[0][3]=Sec10[3];
        Sec[1][0]=Sec10[1]; Sec[1][1]=Sec10[4]; Sec[1][2]=Sec10[5]; Sec[1][3]=Sec10[6];
        Sec[2][0]=Sec10[2]; Sec[2][1]=Sec10[5]; Sec[2][2]=Sec10[7]; Sec[2][3]=Sec10[8];
        Sec[3][0]=Sec10[3]; Sec[3][1]=Sec10[6]; Sec[3][2]=Sec10[8]; Sec[3][3]=Sec10[9];

        float O[3][4];
        for (int a = 0; a < 3; a++)
            for (int b = 0; b < 4; b++) {
                float v = 0.f;
                for (int c = 0; c < 4; c++) v += (F[a*4+c]*norm) * s_Inv[k][c*4+b];
                O[a][b] = v;
            }
        float* go = g_ops + u*SS*KK*12 + t*12;
        for (int i = 0; i < 12; i++) go[i] = O[i/4][i%4];

        // sigma = pn*(XX - F O^T - (F O^T)^T + O Sec O^T) + EPS I
        float H[3][3];
        for (int a = 0; a < 3; a++)
            for (int b = 0; b < 3; b++) {
                float v = 0.f;
                for (int c = 0; c < 4; c++) v += F[a*4+c]*O[b][c];
                H[a][b] = v;
            }
        float G[3][4];
        for (int a = 0; a < 3; a++)
            for (int c = 0; c < 4; c++) {
                float v = 0.f;
                for (int cc = 0; cc < 4; cc++) v += O[a][cc]*Sec[cc][c];
                G[a][c] = v;
            }
        float GO[3][3];
        for (int a = 0; a < 3; a++)
            for (int b = a; b < 3; b++) {
                float v = 0.f;
                for (int c = 0; c < 4; c++) v += G[a][c]*O[b][c];
                GO[a][b] = v;
            }
        const float sa = pn*(XX[0] - 2.f*H[0][0]       + GO[0][0]) + EPSF;
        const float sb = pn*(XX[1] - H[0][1] - H[1][0] + GO[0][1]);
        const float sc = pn*(XX[2] - H[0][2] - H[2][0] + GO[0][2]);
        const float sd = pn*(XX[3] - 2.f*H[1][1]       + GO[1][1]) + EPSF;
        const float se = pn*(XX[4] - H[1][2] - H[2][1] + GO[1][2]);
        const float sf = pn*(XX[5] - 2.f*H[2][2]       + GO[2][2]) + EPSF;

        const float A  = sd*sf - se*se;
        const float Bc = sc*se - sb*sf;
        const float Cc = sb*se - sc*sd;
        const float det = sa*A + sb*Bc + sc*Cc;
        const float idet = 1.f / det;

        float* Si = g_siginv + ((size_t)u*SS*KK + t)*8;
        Si[0] = A*idet;
        Si[1] = Bc*idet;
        Si[2] = Cc*idet;
        Si[3] = (sa*sf - sc*sc)*idet;
        Si[4] = (sb*sc - sa*se)*idet;
        Si[5] = (sa*sd - sb*sb)*idet;
        Si[6] = 0.f; Si[7] = 0.f;

        s_ld48[t] = __logf(det);
    }
    __syncthreads();
    if (t < KK) {
        float v = 0.f;
        for (int s = 0; s < SS; s++) v += s_ld48[s*KK + t];
        g_ldsum[u*KK + t] = v;
    }
}

extern "C" void kernel_launch(void* const* d_in, const int* in_sizes, int n_in,
                              void* d_out, int out_size)
{
    const float* img = nullptr;
    const float* sh = nullptr;
    const float* pred = nullptr;
    for (int i = 0; i < n_in; i++) {
        if (in_sizes[i] == BB*CC*HW)         img  = (const float*)d_in[i];
        else if (in_sizes[i] == BB*SS*CC*HW) sh   = (const float*)d_in[i];
        else if (in_sizes[i] == BB*KK*HW)    pred = (const float*)d_in[i];
    }
    float* out = (float*)d_out;

    dim3 grid(NCHUNK, BB);

    accum_kernel<0><<<grid, NTHREADS>>>(img, sh, pred, out);
    solve_kernel<<<BB, 960>>>();
    accum_kernel<1><<<grid, NTHREADS>>>(img, sh, pred, out);
    solve_kernel<<<BB, 960>>>();
    accum_kernel<1><<<grid, NTHREADS>>>(img, sh, pred, out);
    solve_kernel<<<BB, 960>>>();
    accum_kernel<2><<<grid, NTHREADS>>>(img, sh, pred, out);
}

// round 16
// speedup vs baseline: 1.0100x; 1.0100x over previous
#include <cuda_runtime.h>
#include <math.h>

#define BB 16
#define SS 8
#define CC 3
#define KK 6
#define HW 16384
#define CHUNK 256
#define NCHUNK (HW/CHUNK)     // 64
#define NTHREADS 288          // 9 warps
#define EPSF 1.1920928955078125e-07f

// slot layout (per chunk):
//   F/XX: s*108 + k*18 + j   (j<12: F[a][b], 12..17: XX sym3)  [0,864)
//   Sec:  864 + k*11 + j     (j<10: sym4 Sec, j=10: gp sum)    [864,930)
// Each slot stores 4 sub-partials (3-level warp reduction) as one float4.
#define NSLOT 930
#define NQ 8                   // reduceK groups (8 chunks each)

__device__ float4 g_part4[(size_t)BB*NCHUNK*NSLOT];  // [u][chunk][slot] float4
__device__ float  g_mid[BB*NQ*NSLOT];                // [u][q][slot]
__device__ float  g_ops[BB*SS*KK*12];
__device__ float  g_siginv[BB*SS*KK*8];      // [s00,s01,s02,s11,s12,s22,0,0]
__device__ float  g_ldsum[BB*KK];

// ---------------- packed f32x2 helpers ----------------
typedef unsigned long long u64;
__device__ __forceinline__ u64 pk2(float lo, float hi) {
    u64 r; asm("mov.b64 %0,{%1,%2};" : "=l"(r) : "f"(lo), "f"(hi)); return r;
}
__device__ __forceinline__ u64 bc2(float v) { return pk2(v, v); }
__device__ __forceinline__ void up2(float& lo, float& hi, u64 v) {
    asm("mov.b64 {%0,%1},%2;" : "=f"(lo), "=f"(hi) : "l"(v));
}
__device__ __forceinline__ u64 fma2(u64 a, u64 b, u64 c) {
    u64 d; asm("fma.rn.f32x2 %0,%1,%2,%3;" : "=l"(d) : "l"(a), "l"(b), "l"(c)); return d;
}
__device__ __forceinline__ u64 mul2(u64 a, u64 b) {
    u64 d; asm("mul.rn.f32x2 %0,%1,%2;" : "=l"(d) : "l"(a), "l"(b)); return d;
}
__device__ __forceinline__ u64 add2(u64 a, u64 b) {
    u64 d; asm("add.rn.f32x2 %0,%1,%2;" : "=l"(d) : "l"(a), "l"(b)); return d;
}
__device__ __forceinline__ u64 neg2(u64 a) { return a ^ 0x8000000080000000ULL; }

// 3-level partial warp reduction: lanes 0-3 end with sums of lanes {l, l+4, ..., l+28}
__device__ __forceinline__ u64 red3lvl(u64 v) {
    v = add2(v, __shfl_down_sync(0xffffffffu, v, 16));
    v = add2(v, __shfl_down_sync(0xffffffffu, v, 8));
    v = add2(v, __shfl_down_sync(0xffffffffu, v, 4));
    return v;
}

// MODE 0: softmax(pred) -> gp, accumulate moments
// MODE 1: quad -> gen -> softmax(pred+gen) -> gp, accumulate moments
// MODE 2: quad -> gen -> write output
template<int MODE>
__global__ __launch_bounds__(NTHREADS, 2)
void accum_kernel(const float* __restrict__ img, const float* __restrict__ shifted,
                  const float* __restrict__ pred, float* __restrict__ out)
{
    __shared__ float4 s_sh[SS][CHUNK];     // 32 KB
    __shared__ float4 s_img[CHUNK];        // 4 KB
    __shared__ u64   s_gp2[3][CHUNK];      // 6 KB  (k-pairs packed)
    __shared__ u64   s_ops2[SS*3*12];      // 2.25 KB
    __shared__ u64   s_sinv2[SS*3*6];      // 1.125 KB
    __shared__ float s_ld[KK];

    const int u    = blockIdx.y;
    const int base = blockIdx.x * CHUNK;
    const int tid  = threadIdx.x;

    if (MODE >= 1) {
        const float* go = g_ops + u*SS*KK*12;
        for (int i = tid; i < SS*3*12; i += NTHREADS) {
            const int m = i/12, j = i%12;
            const int s = m/3, kk = m%3;
            s_ops2[i] = pk2(go[(s*KK + 2*kk)*12 + j], go[(s*KK + 2*kk + 1)*12 + j]);
        }
        const float* gs = g_siginv + u*SS*KK*8;
        for (int i = tid; i < SS*3*6; i += NTHREADS) {
            const int m = i/6, j = i%6;
            const int s = m/3, kk = m%3;
            const float sc = (j==1 || j==2 || j==4) ? 2.f : 1.f;
            s_sinv2[i] = pk2(sc*gs[(s*KK + 2*kk)*8 + j], sc*gs[(s*KK + 2*kk + 1)*8 + j]);
        }
        if (tid < KK) s_ld[tid] = g_ldsum[u*KK + tid];
        __syncthreads();
    }

    const float* imgU  = img + (size_t)u*CC*HW;
    const float* shU   = shifted + (size_t)u*SS*CC*HW;
    const float* predU = pred + (size_t)u*KK*HW;

    // ---- phase 1: per-pixel quad / softmax / SMEM staging ----
    if (tid < CHUNK) {
        const int pix = base + tid;
        const float pb0 = imgU[pix];
        const float pb1 = imgU[HW + pix];
        const float pb2 = imgU[2*HW + pix];
        if (MODE < 2) s_img[tid] = make_float4(pb0, pb1, pb2, 1.f);

        const u64 pbb0 = bc2(pb0), pbb1 = bc2(pb1), pbb2 = bc2(pb2);
        u64 q2[3] = {0ULL, 0ULL, 0ULL};

        #pragma unroll
        for (int s = 0; s < SS; s++) {
            const float x0 = shU[(s*CC+0)*HW + pix];
            const float x1 = shU[(s*CC+1)*HW + pix];
            const float x2 = shU[(s*CC+2)*HW + pix];
            if (MODE < 2) s_sh[s][tid] = make_float4(x0, x1, x2, 0.f);
            if (MODE >= 1) {
                const u64 xb0 = bc2(x0), xb1 = bc2(x1), xb2 = bc2(x2);
                #pragma unroll
                for (int kk = 0; kk < 3; kk++) {
                    const u64* O = s_ops2 + (s*3 + kk)*12;
                    const u64 d0 = add2(xb0, neg2(fma2(O[0], pbb0, fma2(O[1], pbb1, fma2(O[2],  pbb2, O[3])))));
                    const u64 d1 = add2(xb1, neg2(fma2(O[4], pbb0, fma2(O[5], pbb1, fma2(O[6],  pbb2, O[7])))));
                    const u64 d2 = add2(xb2, neg2(fma2(O[8], pbb0, fma2(O[9], pbb1, fma2(O[10], pbb2, O[11])))));
                    const u64* Si = s_sinv2 + (s*3 + kk)*6;
                    u64 acc = q2[kk];
                    acc = fma2(Si[0], mul2(d0, d0), acc);
                    acc = fma2(Si[1], mul2(d0, d1), acc);
                    acc = fma2(Si[2], mul2(d0, d2), acc);
                    acc = fma2(Si[3], mul2(d1, d1), acc);
                    acc = fma2(Si[4], mul2(d1, d2), acc);
                    acc = fma2(Si[5], mul2(d2, d2), acc);
                    q2[kk] = acc;
                }
            }
        }

        float q[KK];
        #pragma unroll
        for (int kk = 0; kk < 3; kk++) up2(q[2*kk], q[2*kk+1], q2[kk]);

        if (MODE == 2) {
            #pragma unroll
            for (int k = 0; k < KK; k++)
                out[((size_t)u*KK + k)*HW + pix] = -0.5f*q[k] - 0.5f*s_ld[k];
        } else {
            float lg[KK];
            float mx = -1e30f;
            #pragma unroll
            for (int k = 0; k < KK; k++) {
                const float gen = (MODE >= 1) ? (-0.5f*q[k] - 0.5f*s_ld[k]) : 0.f;
                lg[k] = predU[k*HW + pix] + gen;
                mx = fmaxf(mx, lg[k]);
            }
            float sum = 0.f;
            #pragma unroll
            for (int k = 0; k < KK; k++) { lg[k] = __expf(lg[k] - mx); sum += lg[k]; }
            const float inv = 1.f / sum;
            #pragma unroll
            for (int kk = 0; kk < 3; kk++)
                s_gp2[kk][tid] = pk2(lg[2*kk]*inv + EPSF, lg[2*kk+1]*inv + EPSF);
        }
    }
    if (MODE == 2) return;
    __syncthreads();

    // ---- phase 2: packed moment accumulation ----
    const int warp = tid >> 5, lane = tid & 31;
    float* part = (float*)g_part4 + (size_t)(u*NCHUNK + blockIdx.x)*NSLOT*4;

    if (warp < SS) {
        const int s = warp;
        #pragma unroll 1
        for (int kk = 0; kk < 3; kk++) {
            u64 a[18];
            #pragma unroll
            for (int j = 0; j < 18; j++) a[j] = 0ULL;
            #pragma unroll
            for (int i = 0; i < CHUNK/32; i++) {
                const int p = lane + 32*i;
                const float4 x  = s_sh[s][p];
                const float4 pb = s_img[p];
                const u64 w2 = s_gp2[kk][p];
                const u64 xb0 = bc2(x.x),  xb1 = bc2(x.y),  xb2 = bc2(x.z);
                const u64 pbb0 = bc2(pb.x), pbb1 = bc2(pb.y), pbb2 = bc2(pb.z);
                const u64 t0 = mul2(xb0, w2), t1 = mul2(xb1, w2), t2 = mul2(xb2, w2);
                a[0]  = fma2(t0, pbb0, a[0]);  a[1]  = fma2(t0, pbb1, a[1]);
                a[2]  = fma2(t0, pbb2, a[2]);  a[3]  = add2(a[3], t0);
                a[4]  = fma2(t1, pbb0, a[4]);  a[5]  = fma2(t1, pbb1, a[5]);
                a[6]  = fma2(t1, pbb2, a[6]);  a[7]  = add2(a[7], t1);
                a[8]  = fma2(t2, pbb0, a[8]);  a[9]  = fma2(t2, pbb1, a[9]);
                a[10] = fma2(t2, pbb2, a[10]); a[11] = add2(a[11], t2);
                a[12] = fma2(t0, xb0, a[12]);  a[13] = fma2(t0, xb1, a[13]);
                a[14] = fma2(t0, xb2, a[14]);  a[15] = fma2(t1, xb1, a[15]);
                a[16] = fma2(t1, xb2, a[16]);  a[17] = fma2(t2, xb2, a[17]);
            }
            #pragma unroll
            for (int j = 0; j < 18; j++) {
                const u64 v = red3lvl(a[j]);
                if (lane < 4) {
                    float lo, hi; up2(lo, hi, v);
                    part[(size_t)(s*108 + (2*kk)*18 + j)*4 + lane]   = lo;
                    part[(size_t)(s*108 + (2*kk+1)*18 + j)*4 + lane] = hi;
                }
            }
        }
    } else {
        // warp 8: sym4 Sec moments + gp sums (packed k-pairs)
        #pragma unroll 1
        for (int kk = 0; kk < 3; kk++) {
            u64 a[10];
            #pragma unroll
            for (int j = 0; j < 10; j++) a[j] = 0ULL;
            #pragma unroll
            for (int i = 0; i < CHUNK/32; i++) {
                const int p = lane + 32*i;
                const float4 pb = s_img[p];
                const u64 w2 = s_gp2[kk][p];
                const u64 pbb0 = bc2(pb.x), pbb1 = bc2(pb.y), pbb2 = bc2(pb.z);
                const u64 ww0 = mul2(w2, pbb0), ww1 = mul2(w2, pbb1), ww2 = mul2(w2, pbb2);
                a[0] = fma2(ww0, pbb0, a[0]); a[1] = fma2(ww0, pbb1, a[1]);
                a[2] = fma2(ww0, pbb2, a[2]); a[3] = add2(a[3], ww0);
                a[4] = fma2(ww1, pbb1, a[4]); a[5] = fma2(ww1, pbb2, a[5]);
                a[6] = add2(a[6], ww1);
                a[7] = fma2(ww2, pbb2, a[7]); a[8] = add2(a[8], ww2);
                a[9] = add2(a[9], w2);
            }
            #pragma unroll
            for (int j = 0; j < 10; j++) {
                const u64 v = red3lvl(a[j]);
                if (lane < 4) {
                    float lo, hi; up2(lo, hi, v);
                    part[(size_t)(864 + (2*kk)*11 + j)*4 + lane]   = lo;
                    part[(size_t)(864 + (2*kk+1)*11 + j)*4 + lane] = hi;
                    if (j == 9) {  // gp sum duplicates Sec[3][3]
                        part[(size_t)(864 + (2*kk)*11 + 10)*4 + lane]   = lo;
                        part[(size_t)(864 + (2*kk+1)*11 + 10)*4 + lane] = hi;
                    }
                }
            }
        }
    }
}

// ---------------- stage A: wide parallel partial reduce ----------------
// grid (NQ, BB): block (u, q) sums chunks [q*8, q*8+8) for all slots.
__global__ __launch_bounds__(128)
void reduceK_kernel()
{
    const int u = blockIdx.y;
    const int q = blockIdx.x;
    const int t = threadIdx.x;
    const float4* base = g_part4 + (size_t)(u*NCHUNK + q*(NCHUNK/NQ))*NSLOT;
    for (int slot = t; slot < NSLOT; slot += 128) {
        const float4* p = base + slot;
        float v = 0.f;
        #pragma unroll
        for (int c = 0; c < NCHUNK/NQ; c++) {
            const float4 a = p[(size_t)c*NSLOT];
            v += ((a.x + a.y) + (a.z + a.w));
        }
        g_mid[(u*NQ + q)*NSLOT + slot] = v;
    }
}

// ---------------- stage B: final combine + per-u solve ----------------
__global__ __launch_bounds__(960)
void solve_kernel()
{
    __shared__ float m[NSLOT];
    __shared__ float s_Inv[KK][16];
    __shared__ float s_norm[KK];
    __shared__ float s_pn[KK];
    __shared__ float s_ld48[SS*KK];

    const int u = blockIdx.x;
    const int t = threadIdx.x;

    if (t < NSLOT) {
        const float* p = g_mid + u*NQ*NSLOT + t;
        float v0 = p[0*NSLOT] + p[1*NSLOT];
        float v1 = p[2*NSLOT] + p[3*NSLOT];
        float v2 = p[4*NSLOT] + p[5*NSLOT];
        float v3 = p[6*NSLOT] + p[7*NSLOT];
        m[t] = ((v0 + v1) + (v2 + v3));
    }
    __syncthreads();

    if (t < KK) {
        const int k = t;
        const float* sec = m + 864 + k*11;
        const float trace = sec[0] + sec[4] + sec[7] + sec[9];
        const float norm = 1.f / trace;
        s_norm[k] = norm;
        s_pn[k] = 1.f / sec[10];

        float M[4][4], Inv[4][4];
        M[0][0]=sec[0]; M[0][1]=sec[1]; M[0][2]=sec[2]; M[0][3]=sec[3];
        M[1][0]=sec[1]; M[1][1]=sec[4]; M[1][2]=sec[5]; M[1][3]=sec[6];
        M[2][0]=sec[2]; M[2][1]=sec[5]; M[2][2]=sec[7]; M[2][3]=sec[8];
        M[3][0]=sec[3]; M[3][1]=sec[6]; M[3][2]=sec[8]; M[3][3]=sec[9];
        for (int i = 0; i < 4; i++) {
            for (int j = 0; j < 4; j++) { M[i][j] *= norm; Inv[i][j] = (i==j)?1.f:0.f; }
            M[i][i] += EPSF;
        }
        for (int col = 0; col < 4; col++) {
            int piv = col; float best = fabsf(M[col][col]);
            for (int r = col+1; r < 4; r++) {
                const float v = fabsf(M[r][col]);
                if (v > best) { best = v; piv = r; }
            }
            if (piv != col) {
                for (int j = 0; j < 4; j++) {
                    float tmp=M[col][j]; M[col][j]=M[piv][j]; M[piv][j]=tmp;
                    tmp=Inv[col][j]; Inv[col][j]=Inv[piv][j]; Inv[piv][j]=tmp;
                }
            }
            const float d = 1.f / M[col][col];
            for (int j = 0; j < 4; j++) { M[col][j] *= d; Inv[col][j] *= d; }
            for (int r = 0; r < 4; r++) {
                if (r == col) continue;
                const float f = M[r][col];
                for (int j = 0; j < 4; j++) { M[r][j] -= f*M[col][j]; Inv[r][j] -= f*Inv[col][j]; }
            }
        }
        for (int i = 0; i < 16; i++) s_Inv[k][i] = Inv[i/4][i%4];
    }
    __syncthreads();

    if (t < SS*KK) {
        const int s = t / KK, k = t % KK;
        const float norm = s_norm[k];
        const float pn   = s_pn[k];
        const float* F  = m + s*108 + k*18;   // [3][4]
        const float* XX = F + 12;             // sym3
        const float* Sec10 = m + 864 + k*11;

        float Sec[4][4];
        Sec[0][0]=Sec10[0]; Sec[0][1]=Sec10[1]; Sec[0][2]=Sec10[2]; Sec[0][3]=Sec10[3];
        Sec[1][0]=Sec10[1]; Sec[1][1]=Sec10[4]; Sec[1][2]=Sec10[5]; Sec[1][3]=Sec10[6];
        Sec[2][0]=Sec10[2]; Sec[2][1]=Sec10[5]; Sec[2][2]=Sec10[7]; Sec[2][3]=Sec10[8];
        Sec[3][0]=Sec10[3]; Sec[3][1]=Sec10[6]; Sec[3][2]=Sec10[8]; Sec[3][3]=Sec10[9];

        float O[3][4];
        for (int a = 0; a < 3; a++)
            for (int b = 0; b < 4; b++) {
                float v = 0.f;
                for (int c = 0; c < 4; c++) v += (F[a*4+c]*norm) * s_Inv[k][c*4+b];
                O[a][b] = v;
            }
        float* go = g_ops + u*SS*KK*12 + t*12;
        for (int i = 0; i < 12; i++) go[i] = O[i/4][i%4];

        // sigma = pn*(XX - F O^T - (F O^T)^T + O Sec O^T) + EPS I
        float H[3][3];
        for (int a = 0; a < 3; a++)
            for (int b = 0; b < 3; b++) {
                float v = 0.f;
                for (int c = 0; c < 4; c++) v += F[a*4+c]*O[b][c];
                H[a][b] = v;
            }
        float G[3][4];
        for (int a = 0; a < 3; a++)
            for (int c = 0; c < 4; c++) {
                float v = 0.f;
                for (int cc = 0; cc < 4; cc++) v += O[a][cc]*Sec[cc][c];
                G[a][c] = v;
            }
        float GO[3][3];
        for (int a = 0; a < 3; a++)
            for (int b = a; b < 3; b++) {
                float v = 0.f;
                for (int c = 0; c < 4; c++) v += G[a][c]*O[b][c];
                GO[a][b] = v;
            }
        const float sa = pn*(XX[0] - 2.f*H[0][0]       + GO[0][0]) + EPSF;
        const float sb = pn*(XX[1] - H[0][1] - H[1][0] + GO[0][1]);
        const float sc = pn*(XX[2] - H[0][2] - H[2][0] + GO[0][2]);
        const float sd = pn*(XX[3] - 2.f*H[1][1]       + GO[1][1]) + EPSF;
        const float se = pn*(XX[4] - H[1][2] - H[2][1] + GO[1][2]);
        const float sf = pn*(XX[5] - 2.f*H[2][2]       + GO[2][2]) + EPSF;

        const float A  = sd*sf - se*se;
        const float Bc = sc*se - sb*sf;
        const float Cc = sb*se - sc*sd;
        const float det = sa*A + sb*Bc + sc*Cc;
        const float idet = 1.f / det;

        float* Si = g_siginv + ((size_t)u*SS*KK + t)*8;
        Si[0] = A*idet;
        Si[1] = Bc*idet;
        Si[2] = Cc*idet;
        Si[3] = (sa*sf - sc*sc)*idet;
        Si[4] = (sb*sc - sa*se)*idet;
        Si[5] = (sa*sd - sb*sb)*idet;
        Si[6] = 0.f; Si[7] = 0.f;

        s_ld48[t] = __logf(det);
    }
    __syncthreads();
    if (t < KK) {
        float v = 0.f;
        for (int s = 0; s < SS; s++) v += s_ld48[s*KK + t];
        g_ldsum[u*KK + t] = v;
    }
}

extern "C" void kernel_launch(void* const* d_in, const int* in_sizes, int n_in,
                              void* d_out, int out_size)
{
    const float* img = nullptr;
    const float* sh = nullptr;
    const float* pred = nullptr;
    for (int i = 0; i < n_in; i++) {
        if (in_sizes[i] == BB*CC*HW)         img  = (const float*)d_in[i];
        else if (in_sizes[i] == BB*SS*CC*HW) sh   = (const float*)d_in[i];
        else if (in_sizes[i] == BB*KK*HW)    pred = (const float*)d_in[i];
    }
    float* out = (float*)d_out;

    dim3 grid(NCHUNK, BB);
    dim3 gred(NQ, BB);

    accum_kernel<0><<<grid, NTHREADS>>>(img, sh, pred, out);
    reduceK_kernel<<<gred, 128>>>();
    solve_kernel<<<BB, 960>>>();
    accum_kernel<1><<<grid, NTHREADS>>>(img, sh, pred, out);
    reduceK_kernel<<<gred, 128>>>();
    solve_kernel<<<BB, 960>>>();
    accum_kernel<1><<<grid, NTHREADS>>>(img, sh, pred, out);
    reduceK_kernel<<<gred, 128>>>();
    solve_kernel<<<BB, 960>>>();
    accum_kernel<2><<<grid, NTHREADS>>>(img, sh, pred, out);
}

// round 17
// speedup vs baseline: 1.0622x; 1.0518x over previous
#include <cuda_runtime.h>
#include <math.h>

#define BB 16
#define SS 8
#define CC 3
#define KK 6
#define HW 16384
#define CHUNK 256
#define NCHUNK (HW/CHUNK)     // 64
#define NTHREADS 288          // 9 warps
#define EPSF 1.1920928955078125e-07f

// slot layout (per chunk):
//   F/XX: s*108 + k*18 + j   (j<12: F[a][b], 12..17: XX sym3)  [0,864)
//   Sec:  864 + k*11 + j     (j<10: sym4 Sec, j=10: gp sum)    [864,930)
// Each slot stores 4 sub-partials (3-level warp reduction) as one float4.
#define NSLOT 930

__device__ float4 g_part4[(size_t)BB*NCHUNK*NSLOT];  // [u][chunk][slot] float4
__device__ float  g_ops[BB*SS*KK*12];
__device__ float  g_siginv[BB*SS*KK*8];      // [s00,s01,s02,s11,s12,s22,0,0]
__device__ float  g_ldsum[BB*KK];

// ---------------- packed f32x2 helpers ----------------
typedef unsigned long long u64;
__device__ __forceinline__ u64 pk2(float lo, float hi) {
    u64 r; asm("mov.b64 %0,{%1,%2};" : "=l"(r) : "f"(lo), "f"(hi)); return r;
}
__device__ __forceinline__ u64 bc2(float v) { return pk2(v, v); }
__device__ __forceinline__ void up2(float& lo, float& hi, u64 v) {
    asm("mov.b64 {%0,%1},%2;" : "=f"(lo), "=f"(hi) : "l"(v));
}
__device__ __forceinline__ u64 fma2(u64 a, u64 b, u64 c) {
    u64 d; asm("fma.rn.f32x2 %0,%1,%2,%3;" : "=l"(d) : "l"(a), "l"(b), "l"(c)); return d;
}
__device__ __forceinline__ u64 mul2(u64 a, u64 b) {
    u64 d; asm("mul.rn.f32x2 %0,%1,%2;" : "=l"(d) : "l"(a), "l"(b)); return d;
}
__device__ __forceinline__ u64 add2(u64 a, u64 b) {
    u64 d; asm("add.rn.f32x2 %0,%1,%2;" : "=l"(d) : "l"(a), "l"(b)); return d;
}
__device__ __forceinline__ u64 neg2(u64 a) { return a ^ 0x8000000080000000ULL; }

// 3-level partial warp reduction: lanes 0-3 end with sums of lanes {l, l+4, ..., l+28}
__device__ __forceinline__ u64 red3lvl(u64 v) {
    v = add2(v, __shfl_down_sync(0xffffffffu, v, 16));
    v = add2(v, __shfl_down_sync(0xffffffffu, v, 8));
    v = add2(v, __shfl_down_sync(0xffffffffu, v, 4));
    return v;
}

// MODE 0: softmax(pred) -> gp, accumulate moments
// MODE 1: quad -> gen -> softmax(pred+gen) -> gp, accumulate moments
// MODE 2: quad -> gen -> write output
template<int MODE>
__global__ __launch_bounds__(NTHREADS, 2)
void accum_kernel(const float* __restrict__ img, const float* __restrict__ shifted,
                  const float* __restrict__ pred, float* __restrict__ out)
{
    __shared__ float s_shp[CC][SS][CHUNK];  // 24 KB (planar)
    __shared__ float s_imgp[CC][CHUNK];     // 3 KB  (planar)
    __shared__ u64   s_gp2[3][CHUNK];       // 6 KB  (k-pairs packed)
    __shared__ u64   s_ops2[SS*3*12];       // 2.25 KB
    __shared__ u64   s_sinv2[SS*3*6];       // 1.125 KB
    __shared__ float s_ld[KK];

    const int u    = blockIdx.y;
    const int base = blockIdx.x * CHUNK;
    const int tid  = threadIdx.x;

    if (MODE >= 1) {
        const float* go = g_ops + u*SS*KK*12;
        for (int i = tid; i < SS*3*12; i += NTHREADS) {
            const int m = i/12, j = i%12;
            const int s = m/3, kk = m%3;
            s_ops2[i] = pk2(go[(s*KK + 2*kk)*12 + j], go[(s*KK + 2*kk + 1)*12 + j]);
        }
        const float* gs = g_siginv + u*SS*KK*8;
        for (int i = tid; i < SS*3*6; i += NTHREADS) {
            const int m = i/6, j = i%6;
            const int s = m/3, kk = m%3;
            const float sc = (j==1 || j==2 || j==4) ? 2.f : 1.f;
            s_sinv2[i] = pk2(sc*gs[(s*KK + 2*kk)*8 + j], sc*gs[(s*KK + 2*kk + 1)*8 + j]);
        }
        if (tid < KK) s_ld[tid] = g_ldsum[u*KK + tid];
        __syncthreads();
    }

    const float* imgU  = img + (size_t)u*CC*HW;
    const float* shU   = shifted + (size_t)u*SS*CC*HW;
    const float* predU = pred + (size_t)u*KK*HW;

    // ---- phase 1: per-pixel quad / softmax / SMEM staging ----
    if (tid < CHUNK) {
        const int pix = base + tid;
        const float pb0 = imgU[pix];
        const float pb1 = imgU[HW + pix];
        const float pb2 = imgU[2*HW + pix];
        if (MODE < 2) {
            s_imgp[0][tid] = pb0;
            s_imgp[1][tid] = pb1;
            s_imgp[2][tid] = pb2;
        }

        const u64 pbb0 = bc2(pb0), pbb1 = bc2(pb1), pbb2 = bc2(pb2);
        u64 q2[3] = {0ULL, 0ULL, 0ULL};

        #pragma unroll
        for (int s = 0; s < SS; s++) {
            const float x0 = shU[(s*CC+0)*HW + pix];
            const float x1 = shU[(s*CC+1)*HW + pix];
            const float x2 = shU[(s*CC+2)*HW + pix];
            if (MODE < 2) {
                s_shp[0][s][tid] = x0;
                s_shp[1][s][tid] = x1;
                s_shp[2][s][tid] = x2;
            }
            if (MODE >= 1) {
                const u64 xb0 = bc2(x0), xb1 = bc2(x1), xb2 = bc2(x2);
                #pragma unroll
                for (int kk = 0; kk < 3; kk++) {
                    const u64* O = s_ops2 + (s*3 + kk)*12;
                    const u64 d0 = add2(xb0, neg2(fma2(O[0], pbb0, fma2(O[1], pbb1, fma2(O[2],  pbb2, O[3])))));
                    const u64 d1 = add2(xb1, neg2(fma2(O[4], pbb0, fma2(O[5], pbb1, fma2(O[6],  pbb2, O[7])))));
                    const u64 d2 = add2(xb2, neg2(fma2(O[8], pbb0, fma2(O[9], pbb1, fma2(O[10], pbb2, O[11])))));
                    const u64* Si = s_sinv2 + (s*3 + kk)*6;
                    u64 acc = q2[kk];
                    acc = fma2(Si[0], mul2(d0, d0), acc);
                    acc = fma2(Si[1], mul2(d0, d1), acc);
                    acc = fma2(Si[2], mul2(d0, d2), acc);
                    acc = fma2(Si[3], mul2(d1, d1), acc);
                    acc = fma2(Si[4], mul2(d1, d2), acc);
                    acc = fma2(Si[5], mul2(d2, d2), acc);
                    q2[kk] = acc;
                }
            }
        }

        float q[KK];
        #pragma unroll
        for (int kk = 0; kk < 3; kk++) up2(q[2*kk], q[2*kk+1], q2[kk]);

        if (MODE == 2) {
            #pragma unroll
            for (int k = 0; k < KK; k++)
                out[((size_t)u*KK + k)*HW + pix] = -0.5f*q[k] - 0.5f*s_ld[k];
        } else {
            float lg[KK];
            float mx = -1e30f;
            #pragma unroll
            for (int k = 0; k < KK; k++) {
                const float gen = (MODE >= 1) ? (-0.5f*q[k] - 0.5f*s_ld[k]) : 0.f;
                lg[k] = predU[k*HW + pix] + gen;
                mx = fmaxf(mx, lg[k]);
            }
            float sum = 0.f;
            #pragma unroll
            for (int k = 0; k < KK; k++) { lg[k] = __expf(lg[k] - mx); sum += lg[k]; }
            const float inv = 1.f / sum;
            #pragma unroll
            for (int kk = 0; kk < 3; kk++)
                s_gp2[kk][tid] = pk2(lg[2*kk]*inv + EPSF, lg[2*kk+1]*inv + EPSF);
        }
    }
    if (MODE == 2) return;
    __syncthreads();

    // ---- phase 2: packed moment accumulation ----
    const int warp = tid >> 5, lane = tid & 31;
    float* part = (float*)g_part4 + (size_t)(u*NCHUNK + blockIdx.x)*NSLOT*4;

    if (warp < SS) {
        const int s = warp;
        #pragma unroll 1
        for (int kk = 0; kk < 3; kk++) {
            u64 a[18];
            #pragma unroll
            for (int j = 0; j < 18; j++) a[j] = 0ULL;
            #pragma unroll
            for (int i = 0; i < CHUNK/32; i++) {
                const int p = lane + 32*i;
                const u64 w2 = s_gp2[kk][p];
                const u64 xb0 = bc2(s_shp[0][s][p]);
                const u64 xb1 = bc2(s_shp[1][s][p]);
                const u64 xb2 = bc2(s_shp[2][s][p]);
                const u64 pbb0 = bc2(s_imgp[0][p]);
                const u64 pbb1 = bc2(s_imgp[1][p]);
                const u64 pbb2 = bc2(s_imgp[2][p]);
                const u64 t0 = mul2(xb0, w2), t1 = mul2(xb1, w2), t2 = mul2(xb2, w2);
                a[0]  = fma2(t0, pbb0, a[0]);  a[1]  = fma2(t0, pbb1, a[1]);
                a[2]  = fma2(t0, pbb2, a[2]);  a[3]  = add2(a[3], t0);
                a[4]  = fma2(t1, pbb0, a[4]);  a[5]  = fma2(t1, pbb1, a[5]);
                a[6]  = fma2(t1, pbb2, a[6]);  a[7]  = add2(a[7], t1);
                a[8]  = fma2(t2, pbb0, a[8]);  a[9]  = fma2(t2, pbb1, a[9]);
                a[10] = fma2(t2, pbb2, a[10]); a[11] = add2(a[11], t2);
                a[12] = fma2(t0, xb0, a[12]);  a[13] = fma2(t0, xb1, a[13]);
                a[14] = fma2(t0, xb2, a[14]);  a[15] = fma2(t1, xb1, a[15]);
                a[16] = fma2(t1, xb2, a[16]);  a[17] = fma2(t2, xb2, a[17]);
            }
            #pragma unroll
            for (int j = 0; j < 18; j++) {
                const u64 v = red3lvl(a[j]);
                if (lane < 4) {
                    float lo, hi; up2(lo, hi, v);
                    part[(size_t)(s*108 + (2*kk)*18 + j)*4 + lane]   = lo;
                    part[(size_t)(s*108 + (2*kk+1)*18 + j)*4 + lane] = hi;
                }
            }
        }
    } else {
        // warp 8: sym4 Sec moments + gp sums (packed k-pairs)
        #pragma unroll 1
        for (int kk = 0; kk < 3; kk++) {
            u64 a[10];
            #pragma unroll
            for (int j = 0; j < 10; j++) a[j] = 0ULL;
            #pragma unroll
            for (int i = 0; i < CHUNK/32; i++) {
                const int p = lane + 32*i;
                const u64 w2 = s_gp2[kk][p];
                const u64 pbb0 = bc2(s_imgp[0][p]);
                const u64 pbb1 = bc2(s_imgp[1][p]);
                const u64 pbb2 = bc2(s_imgp[2][p]);
                const u64 ww0 = mul2(w2, pbb0), ww1 = mul2(w2, pbb1), ww2 = mul2(w2, pbb2);
                a[0] = fma2(ww0, pbb0, a[0]); a[1] = fma2(ww0, pbb1, a[1]);
                a[2] = fma2(ww0, pbb2, a[2]); a[3] = add2(a[3], ww0);
                a[4] = fma2(ww1, pbb1, a[4]); a[5] = fma2(ww1, pbb2, a[5]);
                a[6] = add2(a[6], ww1);
                a[7] = fma2(ww2, pbb2, a[7]); a[8] = add2(a[8], ww2);
                a[9] = add2(a[9], w2);
            }
            #pragma unroll
            for (int j = 0; j < 10; j++) {
                const u64 v = red3lvl(a[j]);
                if (lane < 4) {
                    float lo, hi; up2(lo, hi, v);
                    part[(size_t)(864 + (2*kk)*11 + j)*4 + lane]   = lo;
                    part[(size_t)(864 + (2*kk+1)*11 + j)*4 + lane] = hi;
                    if (j == 9) {  // gp sum duplicates Sec[3][3]
                        part[(size_t)(864 + (2*kk)*11 + 10)*4 + lane]   = lo;
                        part[(size_t)(864 + (2*kk+1)*11 + 10)*4 + lane] = hi;
                    }
                }
            }
        }
    }
}

// ---------------- fused reduce + per-u solve (R14 shape) ----------------
__global__ __launch_bounds__(960)
void solve_kernel()
{
    __shared__ float s_q[4][NSLOT];
    __shared__ float m[NSLOT];
    __shared__ float s_Inv[KK][16];
    __shared__ float s_norm[KK];
    __shared__ float s_pn[KK];
    __shared__ float s_ld48[SS*KK];

    const int u = blockIdx.x;
    const int t = threadIdx.x;

    for (int idx = t; idx < 4*NSLOT; idx += 960) {
        const int qq = idx / NSLOT;
        const int slot = idx - qq*NSLOT;
        const float4* p = g_part4 + (size_t)(u*NCHUNK + qq*16)*NSLOT + slot;
        float v = 0.f;
        #pragma unroll
        for (int c = 0; c < 16; c++) {
            const float4 a = p[(size_t)c*NSLOT];
            v += ((a.x + a.y) + (a.z + a.w));
        }
        s_q[qq][slot] = v;
    }
    __syncthreads();
    if (t < NSLOT) m[t] = ((s_q[0][t] + s_q[1][t]) + (s_q[2][t] + s_q[3][t]));
    __syncthreads();

    if (t < KK) {
        const int k = t;
        const float* sec = m + 864 + k*11;
        const float trace = sec[0] + sec[4] + sec[7] + sec[9];
        const float norm = 1.f / trace;
        s_norm[k] = norm;
        s_pn[k] = 1.f / sec[10];

        float M[4][4], Inv[4][4];
        M[0][0]=sec[0]; M[0][1]=sec[1]; M[0][2]=sec[2]; M[0][3]=sec[3];
        M[1][0]=sec[1]; M[1][1]=sec[4]; M[1][2]=sec[5]; M[1][3]=sec[6];
        M[2][0]=sec[2]; M[2][1]=sec[5]; M[2][2]=sec[7]; M[2][3]=sec[8];
        M[3][0]=sec[3]; M[3][1]=sec[6]; M[3][2]=sec[8]; M[3][3]=sec[9];
        for (int i = 0; i < 4; i++) {
            for (int j = 0; j < 4; j++) { M[i][j] *= norm; Inv[i][j] = (i==j)?1.f:0.f; }
            M[i][i] += EPSF;
        }
        for (int col = 0; col < 4; col++) {
            int piv = col; float best = fabsf(M[col][col]);
            for (int r = col+1; r < 4; r++) {
                const float v = fabsf(M[r][col]);
                if (v > best) { best = v; piv = r; }
            }
            if (piv != col) {
                for (int j = 0; j < 4; j++) {
                    float tmp=M[col][j]; M[col][j]=M[piv][j]; M[piv][j]=tmp;
                    tmp=Inv[col][j]; Inv[col][j]=Inv[piv][j]; Inv[piv][j]=tmp;
                }
            }
            const float d = 1.f / M[col][col];
            for (int j = 0; j < 4; j++) { M[col][j] *= d; Inv[col][j] *= d; }
            for (int r = 0; r < 4; r++) {
                if (r == col) continue;
                const float f = M[r][col];
                for (int j = 0; j < 4; j++) { M[r][j] -= f*M[col][j]; Inv[r][j] -= f*Inv[col][j]; }
            }
        }
        for (int i = 0; i < 16; i++) s_Inv[k][i] = Inv[i/4][i%4];
    }
    __syncthreads();

    if (t < SS*KK) {
        const int s = t / KK, k = t % KK;
        const float norm = s_norm[k];
        const float pn   = s_pn[k];
        const float* F  = m + s*108 + k*18;   // [3][4]
        const float* XX = F + 12;             // sym3
        const float* Sec10 = m + 864 + k*11;

        float Sec[4][4];
        Sec[0][0]=Sec10[0]; Sec[0][1]=Sec10[1]; Sec[0][2]=Sec10[2]; Sec[0][3]=Sec10[3];
        Sec[1][0]=Sec10[1]; Sec[1][1]=Sec10[4]; Sec[1][2]=Sec10[5]; Sec[1][3]=Sec10[6];
        Sec[2][0]=Sec10[2]; Sec[2][1]=Sec10[5]; Sec[2][2]=Sec10[7]; Sec[2][3]=Sec10[8];
        Sec[3][0]=Sec10[3]; Sec[3][1]=Sec10[6]; Sec[3][2]=Sec10[8]; Sec[3][3]=Sec10[9];

        float O[3][4];
        for (int a = 0; a < 3; a++)
            for (int b = 0; b < 4; b++) {
                float v = 0.f;
                for (int c = 0; c < 4; c++) v += (F[a*4+c]*norm) * s_Inv[k][c*4+b];
                O[a][b] = v;
            }
        float* go = g_ops + u*SS*KK*12 + t*12;
        for (int i = 0; i < 12; i++) go[i] = O[i/4][i%4];

        // sigma = pn*(XX - F O^T - (F O^T)^T + O Sec O^T) + EPS I
        float H[3][3];
        for (int a = 0; a < 3; a++)
            for (int b = 0; b < 3; b++) {
                float v = 0.f;
                for (int c = 0; c < 4; c++) v += F[a*4+c]*O[b][c];
                H[a][b] = v;
            }
        float G[3][4];
        for (int a = 0; a < 3; a++)
            for (int c = 0; c < 4; c++) {
                float v = 0.f;
                for (int cc = 0; cc < 4; cc++) v += O[a][cc]*Sec[cc][c];
                G[a][c] = v;
            }
        float GO[3][3];
        for (int a = 0; a < 3; a++)
            for (int b = a; b < 3; b++) {
                float v = 0.f;
                for (int c = 0; c < 4; c++) v += G[a][c]*O[b][c];
                GO[a][b] = v;
            }
        const float sa = pn*(XX[0] - 2.f*H[0][0]       + GO[0][0]) + EPSF;
        const float sb = pn*(XX[1] - H[0][1] - H[1][0] + GO[0][1]);
        const float sc = pn*(XX[2] - H[0][2] - H[2][0] + GO[0][2]);
        const float sd = pn*(XX[3] - 2.f*H[1][1]       + GO[1][1]) + EPSF;
        const float se = pn*(XX[4] - H[1][2] - H[2][1] + GO[1][2]);
        const float sf = pn*(XX[5] - 2.f*H[2][2]       + GO[2][2]) + EPSF;

        const float A  = sd*sf - se*se;
        const float Bc = sc*se - sb*sf;
        const float Cc = sb*se - sc*sd;
        const float det = sa*A + sb*Bc + sc*Cc;
        const float idet = 1.f / det;

        float* Si = g_siginv + ((size_t)u*SS*KK + t)*8;
        Si[0] = A*idet;
        Si[1] = Bc*idet;
        Si[2] = Cc*idet;
        Si[3] = (sa*sf - sc*sc)*idet;
        Si[4] = (sb*sc - sa*se)*idet;
        Si[5] = (sa*sd - sb*sb)*idet;
        Si[6] = 0.f; Si[7] = 0.f;

        s_ld48[t] = __logf(det);
    }
    __syncthreads();
    if (t < KK) {
        float v = 0.f;
        for (int s = 0; s < SS; s++) v += s_ld48[s*KK + t];
        g_ldsum[u*KK + t] = v;
    }
}

extern "C" void kernel_launch(void* const* d_in, const int* in_sizes, int n_in,
                              void* d_out, int out_size)
{
    const float* img = nullptr;
    const float* sh = nullptr;
    const float* pred = nullptr;
    for (int i = 0; i < n_in; i++) {
        if (in_sizes[i] == BB*CC*HW)         img  = (const float*)d_in[i];
        else if (in_sizes[i] == BB*SS*CC*HW) sh   = (const float*)d_in[i];
        else if (in_sizes[i] == BB*KK*HW)    pred = (const float*)d_in[i];
    }
    float* out = (float*)d_out;

    dim3 grid(NCHUNK, BB);

    accum_kernel<0><<<grid, NTHREADS>>>(img, sh, pred, out);
    solve_kernel<<<BB, 960>>>();
    accum_kernel<1><<<grid, NTHREADS>>>(img, sh, pred, out);
    solve_kernel<<<BB, 960>>>();
    accum_kernel<1><<<grid, NTHREADS>>>(img, sh, pred, out);
    solve_kernel<<<BB, 960>>>();
    accum_kernel<2><<<grid, NTHREADS>>>(img, sh, pred, out);
}